// round 4
// baseline (speedup 1.0000x reference)
#include <cuda_runtime.h>

#define N_MAX 100000
#define E_MAX 1600000
#define F 128
#define C_OUT 64
#define BN_EPS 1e-5f

typedef unsigned long long ull;

// ---------------- scratch (__device__ globals; no allocation allowed) --------
__device__ float  d_dinv[N_MAX];
__device__ int    d_cnt[N_MAX];
__device__ int    d_off[N_MAX + 1];
__device__ int    d_cur[N_MAX];
__device__ int    d_part[128];
__device__ int    d_partoff[128];
__device__ int2   d_epack[E_MAX];            // {src, float_bits(weight)}
__device__ float  d_t[(size_t)N_MAX * F];
__device__ float  d_hr1[(size_t)N_MAX * F];
__device__ float  d_hr2[(size_t)N_MAX * F];
__device__ float  d_stats[4 * F];            // [sum1,sq1,sum2,sq2]
__device__ float  d_scale1[F], d_shift1[F];
__device__ float  d_scale2[F], d_shift2[F];
__device__ float2 d_Wp1[64 * F];             // K-paired W1
__device__ float2 d_Wp2[64 * F];             // K-paired W2
__device__ float2 d_Wpo[192 * C_OUT];        // K-paired Wout (384-K)

static inline int cdiv(int a, int b) { return (a + b - 1) / b; }

// ---------------- packed f32x2 helpers ---------------------------------------
__device__ __forceinline__ ull ffma2(ull a, ull b, ull c) {
    ull d;
    asm("fma.rn.f32x2 %0, %1, %2, %3;" : "=l"(d) : "l"(a), "l"(b), "l"(c));
    return d;
}
__device__ __forceinline__ float sumpair(ull v) {
    float lo, hi;
    asm("mov.b64 {%0, %1}, %2;" : "=f"(lo), "=f"(hi) : "l"(v));
    return lo + hi;
}

// ---------------- prep: zero counters/stats + pack weights -------------------
__global__ void k_prep(const float* __restrict__ W1, const float* __restrict__ W2,
                       const float* __restrict__ Wout, int n) {
    int idx = blockIdx.x * blockDim.x + threadIdx.x;
    if (idx < n) { d_cnt[idx] = 0; return; }
    idx -= n;
    if (idx < 4 * F) { d_stats[idx] = 0.0f; return; }
    idx -= 4 * F;
    if (idx < 64 * F) {
        int k2 = idx >> 7, j = idx & 127;
        d_Wp1[idx] = make_float2(W1[(2 * k2) * F + j], W1[(2 * k2 + 1) * F + j]);
        return;
    }
    idx -= 64 * F;
    if (idx < 64 * F) {
        int k2 = idx >> 7, j = idx & 127;
        d_Wp2[idx] = make_float2(W2[(2 * k2) * F + j], W2[(2 * k2 + 1) * F + j]);
        return;
    }
    idx -= 64 * F;
    if (idx < 192 * C_OUT) {
        int k2 = idx >> 6, j = idx & 63;
        d_Wpo[idx] = make_float2(Wout[(2 * k2) * C_OUT + j], Wout[(2 * k2 + 1) * C_OUT + j]);
    }
}

// ---------------- degree / norm ----------------------------------------------
__global__ void k_hist(const int* __restrict__ dst, int e) {
    int i = blockIdx.x * blockDim.x + threadIdx.x;
    if (i < e) atomicAdd(&d_cnt[dst[i]], 1);
}

__global__ void k_dinv(int n) {
    int i = blockIdx.x * blockDim.x + threadIdx.x;
    if (i < n) d_dinv[i] = rsqrtf((float)(d_cnt[i] + 1));   // +1 self loop
}

// ---------------- hierarchical scan ------------------------------------------
__global__ void k_part(int n) {
    __shared__ int ws[8];
    int tid = threadIdx.x;
    int base = blockIdx.x * 1024 + tid * 4;
    int s = 0;
#pragma unroll
    for (int t = 0; t < 4; t++) { int i = base + t; if (i < n) s += d_cnt[i]; }
#pragma unroll
    for (int o = 16; o; o >>= 1) s += __shfl_down_sync(0xffffffffu, s, o);
    if ((tid & 31) == 0) ws[tid >> 5] = s;
    __syncthreads();
    if (tid < 8) {
        int v = ws[tid];
#pragma unroll
        for (int o = 4; o; o >>= 1) v += __shfl_down_sync(0xffu, v, o);
        if (tid == 0) d_part[blockIdx.x] = v;
    }
}

__global__ void k_part_scan(int nb, int n, int e) {
    __shared__ int wsum[4];
    int tid = threadIdx.x;                 // 128 threads
    int lane = tid & 31, wid = tid >> 5;
    int v = (tid < nb) ? d_part[tid] : 0;
    int x = v;
#pragma unroll
    for (int o = 1; o < 32; o <<= 1) {
        int y = __shfl_up_sync(0xffffffffu, x, o);
        if (lane >= o) x += y;
    }
    if (lane == 31) wsum[wid] = x;
    __syncthreads();
    int wb = 0;
    if (wid > 0) wb += wsum[0];
    if (wid > 1) wb += wsum[1];
    if (wid > 2) wb += wsum[2];
    d_partoff[tid] = x - v + wb;
    if (tid == 0) d_off[n] = e;
}

__global__ void k_off(int n) {
    __shared__ int ws[8];
    __shared__ int wexcl[8];
    int tid = threadIdx.x;
    int base = blockIdx.x * 1024 + tid * 4;
    int c0 = 0, c1 = 0, c2 = 0, c3 = 0;
    if (base + 0 < n) c0 = d_cnt[base + 0];
    if (base + 1 < n) c1 = d_cnt[base + 1];
    if (base + 2 < n) c2 = d_cnt[base + 2];
    if (base + 3 < n) c3 = d_cnt[base + 3];
    int tsum = c0 + c1 + c2 + c3;
    int lane = tid & 31, wid = tid >> 5;
    int x = tsum;
#pragma unroll
    for (int o = 1; o < 32; o <<= 1) {
        int y = __shfl_up_sync(0xffffffffu, x, o);
        if (lane >= o) x += y;
    }
    if (lane == 31) ws[wid] = x;
    __syncthreads();
    if (tid < 8) {
        int v = ws[tid];
        int xx = v;
#pragma unroll
        for (int o = 1; o < 8; o <<= 1) {
            int y = __shfl_up_sync(0xffu, xx, o);
            if (tid >= o) xx += y;
        }
        wexcl[tid] = xx - v;
    }
    __syncthreads();
    int texcl = d_partoff[blockIdx.x] + wexcl[wid] + (x - tsum);
    int i = base;
    if (i + 0 < n) { d_off[i + 0] = texcl;                d_cur[i + 0] = d_off[i + 0]; }
    if (i + 1 < n) { d_off[i + 1] = texcl + c0;           d_cur[i + 1] = d_off[i + 1]; }
    if (i + 2 < n) { d_off[i + 2] = texcl + c0 + c1;      d_cur[i + 2] = d_off[i + 2]; }
    if (i + 3 < n) { d_off[i + 3] = texcl + c0 + c1 + c2; d_cur[i + 3] = d_off[i + 3]; }
}

__global__ void k_scatter(const int* __restrict__ src, const int* __restrict__ dst, int e) {
    int i = blockIdx.x * blockDim.x + threadIdx.x;
    if (i >= e) return;
    int s = src[i], d = dst[i];
    int pos = atomicAdd(&d_cur[d], 1);
    d_epack[pos] = make_int2(s, __float_as_int(d_dinv[s] * d_dinv[d]));
}

// ---------------- GEMM core (K-paired f32x2) ---------------------------------
// acc[i][j] accumulates (even-K, odd-K) partial sums as packed f32x2.
template <int NOUT, bool BN>
__device__ __forceinline__ void mm_seg(ull (&acc)[4][4], const float* __restrict__ a0,
                                       const float2* __restrict__ wp,
                                       const float* __restrict__ scale,
                                       const float* __restrict__ shift, int tx) {
    const ull* sc2 = (const ull*)scale;
    const ull* sh2 = (const ull*)shift;
#pragma unroll 4
    for (int k4 = 0; k4 < 32; k4++) {
        ulonglong2 a01[4];
#pragma unroll
        for (int i = 0; i < 4; i++)
            a01[i] = *(const ulonglong2*)(a0 + (size_t)i * F + 4 * k4);
        if (BN) {
            ull s0 = sc2[2 * k4], s1 = sc2[2 * k4 + 1];
            ull h0 = sh2[2 * k4], h1 = sh2[2 * k4 + 1];
#pragma unroll
            for (int i = 0; i < 4; i++) {
                a01[i].x = ffma2(a01[i].x, s0, h0);
                a01[i].y = ffma2(a01[i].y, s1, h1);
            }
        }
#pragma unroll
        for (int p = 0; p < 2; p++) {
            const float2* wr = wp + (size_t)(2 * k4 + p) * NOUT + tx * 4;
            ulonglong2 b01 = *(const ulonglong2*)wr;
            ulonglong2 b23 = *(const ulonglong2*)(wr + 2);
#pragma unroll
            for (int i = 0; i < 4; i++) {
                ull av = p ? a01[i].y : a01[i].x;
                acc[i][0] = ffma2(av, b01.x, acc[i][0]);
                acc[i][1] = ffma2(av, b01.y, acc[i][1]);
                acc[i][2] = ffma2(av, b23.x, acc[i][2]);
                acc[i][3] = ffma2(av, b23.y, acc[i][3]);
            }
        }
    }
}

// C[n,128] = (BN(A))[n,128] @ W[128,128]
template <bool BN>
__global__ __launch_bounds__(256) void k_gemm128p(const float* __restrict__ A,
                                                  const float2* __restrict__ Wp,
                                                  float* __restrict__ C, int n,
                                                  const float* __restrict__ scale,
                                                  const float* __restrict__ shift) {
    const int tx = threadIdx.x & 31;
    const int ty = threadIdx.x >> 5;
    const int row0 = blockIdx.x * 32 + ty * 4;
    if (row0 >= n) return;
    ull acc[4][4] = {};
    mm_seg<F, BN>(acc, A + (size_t)row0 * F, Wp, scale, shift, tx);
#pragma unroll
    for (int i = 0; i < 4; i++) {
        float4 r = make_float4(sumpair(acc[i][0]), sumpair(acc[i][1]),
                               sumpair(acc[i][2]), sumpair(acc[i][3]));
        *(float4*)(C + (size_t)(row0 + i) * F + tx * 4) = r;
    }
}

// C[n,64] = [x, BN1(h1), BN2(h2)] @ Wout[384,64]  (fused 3 segments)
__global__ __launch_bounds__(256) void k_gemm_out(const float* __restrict__ x,
                                                  const float* __restrict__ h1,
                                                  const float* __restrict__ h2,
                                                  float* __restrict__ C, int n,
                                                  const float* __restrict__ sc1,
                                                  const float* __restrict__ sh1,
                                                  const float* __restrict__ sc2,
                                                  const float* __restrict__ sh2) {
    const int tx = threadIdx.x & 15;
    const int ty = threadIdx.x >> 4;
    const int row0 = blockIdx.x * 64 + ty * 4;
    if (row0 >= n) return;
    ull acc[4][4] = {};
    mm_seg<C_OUT, false>(acc, x  + (size_t)row0 * F, d_Wpo,              nullptr, nullptr, tx);
    mm_seg<C_OUT, true >(acc, h1 + (size_t)row0 * F, d_Wpo + 64 * C_OUT,  sc1, sh1, tx);
    mm_seg<C_OUT, true >(acc, h2 + (size_t)row0 * F, d_Wpo + 128 * C_OUT, sc2, sh2, tx);
#pragma unroll
    for (int i = 0; i < 4; i++) {
        float4 r = make_float4(sumpair(acc[i][0]), sumpair(acc[i][1]),
                               sumpair(acc[i][2]), sumpair(acc[i][3]));
        *(float4*)(C + (size_t)(row0 + i) * C_OUT + tx * 4) = r;
    }
}

// ---------------- fused aggregation (F=128) ----------------------------------
__global__ __launch_bounds__(256) void k_agg128(const float* __restrict__ t,
                                                const float* __restrict__ bias,
                                                float* __restrict__ h, int n,
                                                float* __restrict__ stats) {
    const int lane = threadIdx.x & 31;
    const int warp = (blockIdx.x * blockDim.x + threadIdx.x) >> 5;
    const int nwarp = (gridDim.x * blockDim.x) >> 5;
    float4 b = ((const float4*)bias)[lane];
    float s0 = 0, s1 = 0, s2 = 0, s3 = 0;
    float q0 = 0, q1 = 0, q2 = 0, q3 = 0;
    const int l4 = lane * 4;
    for (int v = warp; v < n; v += nwarp) {
        float dv = d_dinv[v];
        float w0 = dv * dv;
        float4 acc = *(const float4*)(t + (size_t)v * F + l4);
        acc.x *= w0; acc.y *= w0; acc.z *= w0; acc.w *= w0;
        int j = d_off[v];
        const int end = d_off[v + 1];
        for (; j + 4 <= end; j += 4) {
            int2 p0 = __ldg(d_epack + j),     p1 = __ldg(d_epack + j + 1);
            int2 p2 = __ldg(d_epack + j + 2), p3 = __ldg(d_epack + j + 3);
            float4 r0 = *(const float4*)(t + (size_t)p0.x * F + l4);
            float4 r1 = *(const float4*)(t + (size_t)p1.x * F + l4);
            float4 r2 = *(const float4*)(t + (size_t)p2.x * F + l4);
            float4 r3 = *(const float4*)(t + (size_t)p3.x * F + l4);
            float e0 = __int_as_float(p0.y), e1 = __int_as_float(p1.y);
            float e2 = __int_as_float(p2.y), e3 = __int_as_float(p3.y);
            acc.x = fmaf(e0, r0.x, acc.x); acc.y = fmaf(e0, r0.y, acc.y);
            acc.z = fmaf(e0, r0.z, acc.z); acc.w = fmaf(e0, r0.w, acc.w);
            acc.x = fmaf(e1, r1.x, acc.x); acc.y = fmaf(e1, r1.y, acc.y);
            acc.z = fmaf(e1, r1.z, acc.z); acc.w = fmaf(e1, r1.w, acc.w);
            acc.x = fmaf(e2, r2.x, acc.x); acc.y = fmaf(e2, r2.y, acc.y);
            acc.z = fmaf(e2, r2.z, acc.z); acc.w = fmaf(e2, r2.w, acc.w);
            acc.x = fmaf(e3, r3.x, acc.x); acc.y = fmaf(e3, r3.y, acc.y);
            acc.z = fmaf(e3, r3.z, acc.z); acc.w = fmaf(e3, r3.w, acc.w);
        }
        for (; j < end; j++) {
            int2 p = __ldg(d_epack + j);
            float w = __int_as_float(p.y);
            float4 r = *(const float4*)(t + (size_t)p.x * F + l4);
            acc.x = fmaf(w, r.x, acc.x); acc.y = fmaf(w, r.y, acc.y);
            acc.z = fmaf(w, r.z, acc.z); acc.w = fmaf(w, r.w, acc.w);
        }
        acc.x = fmaxf(acc.x + b.x, 0.0f);
        acc.y = fmaxf(acc.y + b.y, 0.0f);
        acc.z = fmaxf(acc.z + b.z, 0.0f);
        acc.w = fmaxf(acc.w + b.w, 0.0f);
        *(float4*)(h + (size_t)v * F + l4) = acc;
        s0 += acc.x; s1 += acc.y; s2 += acc.z; s3 += acc.w;
        q0 += acc.x * acc.x; q1 += acc.y * acc.y;
        q2 += acc.z * acc.z; q3 += acc.w * acc.w;
    }
    atomicAdd(&stats[l4 + 0], s0); atomicAdd(&stats[l4 + 1], s1);
    atomicAdd(&stats[l4 + 2], s2); atomicAdd(&stats[l4 + 3], s3);
    atomicAdd(&stats[F + l4 + 0], q0); atomicAdd(&stats[F + l4 + 1], q1);
    atomicAdd(&stats[F + l4 + 2], q2); atomicAdd(&stats[F + l4 + 3], q3);
}

// ---------------- fused aggregation (F=64, final) ----------------------------
__global__ __launch_bounds__(256) void k_agg64(const float* __restrict__ t,
                                               const float* __restrict__ bias,
                                               float* __restrict__ out, int n) {
    const int lane = threadIdx.x & 31;
    const int warp = (blockIdx.x * blockDim.x + threadIdx.x) >> 5;
    const int nwarp = (gridDim.x * blockDim.x) >> 5;
    float2 b = ((const float2*)bias)[lane];
    const int l2 = lane * 2;
    for (int v = warp; v < n; v += nwarp) {
        float dv = d_dinv[v];
        float w0 = dv * dv;
        float2 acc = *(const float2*)(t + (size_t)v * C_OUT + l2);
        acc.x *= w0; acc.y *= w0;
        int j = d_off[v];
        const int end = d_off[v + 1];
        for (; j + 4 <= end; j += 4) {
            int2 p0 = __ldg(d_epack + j),     p1 = __ldg(d_epack + j + 1);
            int2 p2 = __ldg(d_epack + j + 2), p3 = __ldg(d_epack + j + 3);
            float2 r0 = *(const float2*)(t + (size_t)p0.x * C_OUT + l2);
            float2 r1 = *(const float2*)(t + (size_t)p1.x * C_OUT + l2);
            float2 r2 = *(const float2*)(t + (size_t)p2.x * C_OUT + l2);
            float2 r3 = *(const float2*)(t + (size_t)p3.x * C_OUT + l2);
            float e0 = __int_as_float(p0.y), e1 = __int_as_float(p1.y);
            float e2 = __int_as_float(p2.y), e3 = __int_as_float(p3.y);
            acc.x = fmaf(e0, r0.x, acc.x); acc.y = fmaf(e0, r0.y, acc.y);
            acc.x = fmaf(e1, r1.x, acc.x); acc.y = fmaf(e1, r1.y, acc.y);
            acc.x = fmaf(e2, r2.x, acc.x); acc.y = fmaf(e2, r2.y, acc.y);
            acc.x = fmaf(e3, r3.x, acc.x); acc.y = fmaf(e3, r3.y, acc.y);
        }
        for (; j < end; j++) {
            int2 p = __ldg(d_epack + j);
            float w = __int_as_float(p.y);
            float2 r = *(const float2*)(t + (size_t)p.x * C_OUT + l2);
            acc.x = fmaf(w, r.x, acc.x); acc.y = fmaf(w, r.y, acc.y);
        }
        acc.x = fmaxf(acc.x + b.x, 0.0f);
        acc.y = fmaxf(acc.y + b.y, 0.0f);
        *(float2*)(out + (size_t)v * C_OUT + l2) = acc;
    }
}

// ---------------- BN ----------------------------------------------------------
__global__ void k_bn_finalize(const float* __restrict__ stats,
                              const float* __restrict__ gamma,
                              const float* __restrict__ beta,
                              float* __restrict__ scale, float* __restrict__ shift,
                              int n) {
    int c = threadIdx.x;                    // 128 threads
    float inv_n = 1.0f / (float)n;
    float m = stats[c] * inv_n;
    float var = stats[F + c] * inv_n - m * m;
    float rstd = rsqrtf(var + BN_EPS);
    float sc = gamma[c] * rstd;
    scale[c] = sc;
    shift[c] = beta[c] - sc * m;
}

// ---------------- launch ------------------------------------------------------
extern "C" void kernel_launch(void* const* d_in, const int* in_sizes, int n_in,
                              void* d_out, int out_size) {
    const float* x     = (const float*)d_in[0];
    const int*   ei    = (const int*)d_in[1];
    const float* W1    = (const float*)d_in[2];
    const float* b1    = (const float*)d_in[3];
    const float* W2    = (const float*)d_in[4];
    const float* b2    = (const float*)d_in[5];
    const float* Wout  = (const float*)d_in[6];
    const float* bout  = (const float*)d_in[7];
    const float* gamma = (const float*)d_in[8];
    const float* beta  = (const float*)d_in[9];
    float* out = (float*)d_out;

    const int n = in_sizes[0] / F;
    const int e = in_sizes[1] / 2;
    const int* src = ei;
    const int* dst = ei + e;
    const int nb = cdiv(n, 1024);

    float *t, *hr1, *hr2, *sc1, *sh1, *sc2, *sh2, *stats;
    float2 *wp1, *wp2;
    cudaGetSymbolAddress((void**)&t, d_t);
    cudaGetSymbolAddress((void**)&hr1, d_hr1);
    cudaGetSymbolAddress((void**)&hr2, d_hr2);
    cudaGetSymbolAddress((void**)&sc1, d_scale1);
    cudaGetSymbolAddress((void**)&sh1, d_shift1);
    cudaGetSymbolAddress((void**)&sc2, d_scale2);
    cudaGetSymbolAddress((void**)&sh2, d_shift2);
    cudaGetSymbolAddress((void**)&stats, d_stats);
    cudaGetSymbolAddress((void**)&wp1, d_Wp1);
    cudaGetSymbolAddress((void**)&wp2, d_Wp2);

    const int TB = 256;
    const int AGG_BLOCKS = 1024;
    const int prep_items = n + 4 * F + 64 * F * 2 + 192 * C_OUT;

    // 1: prep (zero cnt/stats, pack weights)
    k_prep<<<cdiv(prep_items, TB), TB>>>(W1, W2, Wout, n);
    // 2: degree histogram
    k_hist<<<cdiv(e, TB), TB>>>(dst, e);
    // 3: dinv
    k_dinv<<<cdiv(n, TB), TB>>>(n);
    // 4: layer-1 GEMM (independent of CSR)
    k_gemm128p<false><<<cdiv(n, 32), TB>>>(x, wp1, t, n, nullptr, nullptr);
    // 5-7: hierarchical scan
    k_part<<<nb, TB>>>(n);
    k_part_scan<<<1, 128>>>(nb, n, e);
    k_off<<<nb, TB>>>(n);
    // 8: CSR scatter
    k_scatter<<<cdiv(e, TB), TB>>>(src, dst, e);
    // 9-10: layer-1 aggregation + BN
    k_agg128<<<AGG_BLOCKS, TB>>>(t, b1, hr1, n, stats);
    k_bn_finalize<<<1, 128>>>(stats, gamma, beta, sc1, sh1, n);
    // 11-13: layer-2
    k_gemm128p<true><<<cdiv(n, 32), TB>>>(hr1, wp2, t, n, sc1, sh1);
    k_agg128<<<AGG_BLOCKS, TB>>>(t, b2, hr2, n, stats + 2 * F);
    k_bn_finalize<<<1, 128>>>(stats + 2 * F, gamma, beta, sc2, sh2, n);
    // 14-15: output layer
    k_gemm_out<<<cdiv(n, 64), TB>>>(x, hr1, hr2, t, n, sc1, sh1, sc2, sh2);
    k_agg64<<<AGG_BLOCKS, TB>>>(t, bout, out, n);
}

// round 6
// speedup vs baseline: 1.1268x; 1.1268x over previous
#include <cuda_runtime.h>

#define N_MAX 100000
#define E_MAX 1600000
#define F 128
#define C_OUT 64
#define BN_EPS 1e-5f

typedef unsigned long long ull;

// ---------------- scratch (__device__ globals; no allocation allowed) --------
__device__ float  d_dinv[N_MAX];
__device__ int    d_cnt[N_MAX];
__device__ int    d_off[N_MAX + 1];
__device__ int    d_cur[N_MAX];
__device__ int    d_part[128];
__device__ int    d_partoff[128];
__device__ int2   d_epack[E_MAX];            // {src, float_bits(weight)}
__device__ float  d_t[(size_t)N_MAX * F];
__device__ float  d_hr1[(size_t)N_MAX * F];
__device__ float  d_hr2[(size_t)N_MAX * F];
__device__ float  d_stats[4 * F];            // [sum1,sq1,sum2,sq2]
__device__ float  d_scale1[F], d_shift1[F];
__device__ float  d_scale2[F], d_shift2[F];
__device__ float2 d_Wp1[64 * F];             // K-paired W1
__device__ float2 d_Wp2[64 * F];             // K-paired W2
__device__ float2 d_Wpo[192 * C_OUT];        // K-paired Wout (384-K)

static inline int cdiv(int a, int b) { return (a + b - 1) / b; }

// ---------------- packed f32x2 helpers ---------------------------------------
__device__ __forceinline__ ull ffma2(ull a, ull b, ull c) {
    ull d;
    asm("fma.rn.f32x2 %0, %1, %2, %3;" : "=l"(d) : "l"(a), "l"(b), "l"(c));
    return d;
}
__device__ __forceinline__ float sumpair(ull v) {
    float lo, hi;
    asm("mov.b64 {%0, %1}, %2;" : "=f"(lo), "=f"(hi) : "l"(v));
    return lo + hi;
}

// ---------------- prep: zero counters/stats + pack weights -------------------
__global__ void k_prep(const float* __restrict__ W1, const float* __restrict__ W2,
                       const float* __restrict__ Wout, int n) {
    int idx = blockIdx.x * blockDim.x + threadIdx.x;
    if (idx < n) { d_cnt[idx] = 0; return; }
    idx -= n;
    if (idx < 4 * F) { d_stats[idx] = 0.0f; return; }
    idx -= 4 * F;
    if (idx < 64 * F) {
        int k2 = idx >> 7, j = idx & 127;
        d_Wp1[idx] = make_float2(W1[(2 * k2) * F + j], W1[(2 * k2 + 1) * F + j]);
        return;
    }
    idx -= 64 * F;
    if (idx < 64 * F) {
        int k2 = idx >> 7, j = idx & 127;
        d_Wp2[idx] = make_float2(W2[(2 * k2) * F + j], W2[(2 * k2 + 1) * F + j]);
        return;
    }
    idx -= 64 * F;
    if (idx < 192 * C_OUT) {
        int k2 = idx >> 6, j = idx & 63;
        d_Wpo[idx] = make_float2(Wout[(2 * k2) * C_OUT + j], Wout[(2 * k2 + 1) * C_OUT + j]);
    }
}

// ---------------- degree / norm ----------------------------------------------
__global__ void k_hist(const int* __restrict__ dst, int e) {
    int i = blockIdx.x * blockDim.x + threadIdx.x;
    if (i < e) atomicAdd(&d_cnt[dst[i]], 1);
}

__global__ void k_dinv(int n) {
    int i = blockIdx.x * blockDim.x + threadIdx.x;
    if (i < n) d_dinv[i] = rsqrtf((float)(d_cnt[i] + 1));   // +1 self loop
}

// ---------------- hierarchical scan ------------------------------------------
__global__ void k_part(int n) {
    __shared__ int ws[8];
    int tid = threadIdx.x;
    int base = blockIdx.x * 1024 + tid * 4;
    int s = 0;
#pragma unroll
    for (int t = 0; t < 4; t++) { int i = base + t; if (i < n) s += d_cnt[i]; }
#pragma unroll
    for (int o = 16; o; o >>= 1) s += __shfl_down_sync(0xffffffffu, s, o);
    if ((tid & 31) == 0) ws[tid >> 5] = s;
    __syncthreads();
    if (tid < 8) {
        int v = ws[tid];
#pragma unroll
        for (int o = 4; o; o >>= 1) v += __shfl_down_sync(0xffu, v, o);
        if (tid == 0) d_part[blockIdx.x] = v;
    }
}

__global__ void k_part_scan(int nb, int n, int e) {
    __shared__ int wsum[4];
    int tid = threadIdx.x;                 // 128 threads
    int lane = tid & 31, wid = tid >> 5;
    int v = (tid < nb) ? d_part[tid] : 0;
    int x = v;
#pragma unroll
    for (int o = 1; o < 32; o <<= 1) {
        int y = __shfl_up_sync(0xffffffffu, x, o);
        if (lane >= o) x += y;
    }
    if (lane == 31) wsum[wid] = x;
    __syncthreads();
    int wb = 0;
    if (wid > 0) wb += wsum[0];
    if (wid > 1) wb += wsum[1];
    if (wid > 2) wb += wsum[2];
    d_partoff[tid] = x - v + wb;
    if (tid == 0) d_off[n] = e;
}

__global__ void k_off(int n) {
    __shared__ int ws[8];
    __shared__ int wexcl[8];
    int tid = threadIdx.x;
    int base = blockIdx.x * 1024 + tid * 4;
    int c0 = 0, c1 = 0, c2 = 0, c3 = 0;
    if (base + 0 < n) c0 = d_cnt[base + 0];
    if (base + 1 < n) c1 = d_cnt[base + 1];
    if (base + 2 < n) c2 = d_cnt[base + 2];
    if (base + 3 < n) c3 = d_cnt[base + 3];
    int tsum = c0 + c1 + c2 + c3;
    int lane = tid & 31, wid = tid >> 5;
    int x = tsum;
#pragma unroll
    for (int o = 1; o < 32; o <<= 1) {
        int y = __shfl_up_sync(0xffffffffu, x, o);
        if (lane >= o) x += y;
    }
    if (lane == 31) ws[wid] = x;
    __syncthreads();
    if (tid < 8) {
        int v = ws[tid];
        int xx = v;
#pragma unroll
        for (int o = 1; o < 8; o <<= 1) {
            int y = __shfl_up_sync(0xffu, xx, o);
            if (tid >= o) xx += y;
        }
        wexcl[tid] = xx - v;
    }
    __syncthreads();
    int texcl = d_partoff[blockIdx.x] + wexcl[wid] + (x - tsum);
    int i = base;
    if (i + 0 < n) { d_off[i + 0] = texcl;                d_cur[i + 0] = d_off[i + 0]; }
    if (i + 1 < n) { d_off[i + 1] = texcl + c0;           d_cur[i + 1] = d_off[i + 1]; }
    if (i + 2 < n) { d_off[i + 2] = texcl + c0 + c1;      d_cur[i + 2] = d_off[i + 2]; }
    if (i + 3 < n) { d_off[i + 3] = texcl + c0 + c1 + c2; d_cur[i + 3] = d_off[i + 3]; }
}

__global__ void k_scatter(const int* __restrict__ src, const int* __restrict__ dst, int e) {
    int i = blockIdx.x * blockDim.x + threadIdx.x;
    if (i >= e) return;
    int s = src[i], d = dst[i];
    int pos = atomicAdd(&d_cur[d], 1);
    d_epack[pos] = make_int2(s, __float_as_int(d_dinv[s] * d_dinv[d]));
}

// ---------------- GEMM core: smem-W, TM=8, f32x2 ------------------------------
// Processes NK4 iterations of 4 K-values; W pairs staged in smem (sW[k2][0..NOUT)).
// a0 pre-offset to the K-window start; sc2/sh2 pre-offset likewise.
template <int NOUT, bool BN, int NK4>
__device__ __forceinline__ void mm_core(ull (&acc)[8][4], const float* __restrict__ a0,
                                        const ull* sW,
                                        const ull* __restrict__ sc2,
                                        const ull* __restrict__ sh2, int tx) {
#pragma unroll 2
    for (int k4 = 0; k4 < NK4; k4++) {
        ulonglong2 a[8];
#pragma unroll
        for (int i = 0; i < 8; i++)
            a[i] = *(const ulonglong2*)(a0 + (size_t)i * F + 4 * k4);
        if (BN) {
            ull s0 = sc2[2 * k4], s1 = sc2[2 * k4 + 1];
            ull h0 = sh2[2 * k4], h1 = sh2[2 * k4 + 1];
#pragma unroll
            for (int i = 0; i < 8; i++) {
                a[i].x = ffma2(a[i].x, s0, h0);
                a[i].y = ffma2(a[i].y, s1, h1);
            }
        }
#pragma unroll
        for (int p = 0; p < 2; p++) {
            const ull* wr = sW + (2 * k4 + p) * NOUT + tx * 4;
            ulonglong2 b01 = *(const ulonglong2*)wr;
            ulonglong2 b23 = *(const ulonglong2*)(wr + 2);
#pragma unroll
            for (int i = 0; i < 8; i++) {
                ull av = p ? a[i].y : a[i].x;
                acc[i][0] = ffma2(av, b01.x, acc[i][0]);
                acc[i][1] = ffma2(av, b01.y, acc[i][1]);
                acc[i][2] = ffma2(av, b23.x, acc[i][2]);
                acc[i][3] = ffma2(av, b23.y, acc[i][3]);
            }
        }
    }
}

// C[n,128] = (BN(A))[n,128] @ W[128,128];  W staged in 2 smem halves of 32KB
template <bool BN>
__global__ __launch_bounds__(256, 2) void k_gemm128s(const float* __restrict__ A,
                                                     const float2* __restrict__ Wp,
                                                     float* __restrict__ C, int n,
                                                     const float* __restrict__ scale,
                                                     const float* __restrict__ shift) {
    __shared__ ull sW[32 * F];               // 32 k2-rows x 128 cols = 32KB
    const int tid = threadIdx.x;
    const int tx = tid & 31;
    const int ty = tid >> 5;                 // 8 row-groups
    const int row0 = blockIdx.x * 64 + ty * 8;
    const bool valid = row0 < n;             // n % 8 == 0 -> whole group valid
    const float* a0 = A + (size_t)row0 * F;
    const ull* sc2 = (const ull*)scale;
    const ull* sh2 = (const ull*)shift;
    ull acc[8][4] = {};
#pragma unroll
    for (int half = 0; half < 2; half++) {
        const ulonglong2* wg = (const ulonglong2*)(Wp + half * 32 * F);
#pragma unroll
        for (int i = tid; i < 32 * F / 2; i += 256)
            ((ulonglong2*)sW)[i] = wg[i];
        __syncthreads();
        if (valid)
            mm_core<F, BN, 16>(acc, a0 + half * 64, sW,
                               sc2 + half * 32, sh2 + half * 32, tx);
        __syncthreads();
    }
    if (!valid) return;
#pragma unroll
    for (int i = 0; i < 8; i++) {
        float4 r = make_float4(sumpair(acc[i][0]), sumpair(acc[i][1]),
                               sumpair(acc[i][2]), sumpair(acc[i][3]));
        *(float4*)(C + (size_t)(row0 + i) * F + tx * 4) = r;
    }
}

// C[n,64] = [x, BN1(h1), BN2(h2)] @ Wout[384,64]; each 32KB W segment staged
__global__ __launch_bounds__(256, 2) void k_gemm_outs(const float* __restrict__ x,
                                                      const float* __restrict__ h1,
                                                      const float* __restrict__ h2,
                                                      float* __restrict__ C, int n,
                                                      const float* __restrict__ sc1,
                                                      const float* __restrict__ sh1,
                                                      const float* __restrict__ sc2,
                                                      const float* __restrict__ sh2) {
    __shared__ ull sW[64 * C_OUT];           // 64 k2-rows x 64 cols = 32KB
    const int tid = threadIdx.x;
    const int tx = tid & 15;                 // 16 col-groups of 4
    const int ty = tid >> 4;                 // 16 row-groups
    const int row0 = blockIdx.x * 128 + ty * 8;
    const bool valid = row0 < n;
    const float* segA[3] = {x, h1, h2};
    const ull* segS[3] = {nullptr, (const ull*)sc1, (const ull*)sc2};
    const ull* segH[3] = {nullptr, (const ull*)sh1, (const ull*)sh2};
    ull acc[8][4] = {};
#pragma unroll
    for (int seg = 0; seg < 3; seg++) {
        const ulonglong2* wg = (const ulonglong2*)((const float2*)d_Wpo + seg * 64 * C_OUT);
#pragma unroll
        for (int i = tid; i < 64 * C_OUT / 2; i += 256)
            ((ulonglong2*)sW)[i] = wg[i];
        __syncthreads();
        if (valid) {
            const float* a0 = segA[seg] + (size_t)row0 * F;
            if (seg == 0)
                mm_core<C_OUT, false, 32>(acc, a0, sW, nullptr, nullptr, tx);
            else
                mm_core<C_OUT, true, 32>(acc, a0, sW, segS[seg], segH[seg], tx);
        }
        __syncthreads();
    }
    if (!valid) return;
#pragma unroll
    for (int i = 0; i < 8; i++) {
        float4 r = make_float4(sumpair(acc[i][0]), sumpair(acc[i][1]),
                               sumpair(acc[i][2]), sumpair(acc[i][3]));
        *(float4*)(C + (size_t)(row0 + i) * C_OUT + tx * 4) = r;
    }
}

// ---------------- fused aggregation (F=128) ----------------------------------
__global__ __launch_bounds__(256) void k_agg128(const float* __restrict__ t,
                                                const float* __restrict__ bias,
                                                float* __restrict__ h, int n,
                                                float* __restrict__ stats) {
    const int lane = threadIdx.x & 31;
    const int warp = (blockIdx.x * blockDim.x + threadIdx.x) >> 5;
    const int nwarp = (gridDim.x * blockDim.x) >> 5;
    float4 b = ((const float4*)bias)[lane];
    float s0 = 0, s1 = 0, s2 = 0, s3 = 0;
    float q0 = 0, q1 = 0, q2 = 0, q3 = 0;
    const int l4 = lane * 4;
    for (int v = warp; v < n; v += nwarp) {
        float dv = d_dinv[v];
        float w0 = dv * dv;
        float4 acc = *(const float4*)(t + (size_t)v * F + l4);
        acc.x *= w0; acc.y *= w0; acc.z *= w0; acc.w *= w0;
        int j = d_off[v];
        const int end = d_off[v + 1];
        for (; j + 4 <= end; j += 4) {
            int2 p0 = __ldg(d_epack + j),     p1 = __ldg(d_epack + j + 1);
            int2 p2 = __ldg(d_epack + j + 2), p3 = __ldg(d_epack + j + 3);
            float4 r0 = *(const float4*)(t + (size_t)p0.x * F + l4);
            float4 r1 = *(const float4*)(t + (size_t)p1.x * F + l4);
            float4 r2 = *(const float4*)(t + (size_t)p2.x * F + l4);
            float4 r3 = *(const float4*)(t + (size_t)p3.x * F + l4);
            float e0 = __int_as_float(p0.y), e1 = __int_as_float(p1.y);
            float e2 = __int_as_float(p2.y), e3 = __int_as_float(p3.y);
            acc.x = fmaf(e0, r0.x, acc.x); acc.y = fmaf(e0, r0.y, acc.y);
            acc.z = fmaf(e0, r0.z, acc.z); acc.w = fmaf(e0, r0.w, acc.w);
            acc.x = fmaf(e1, r1.x, acc.x); acc.y = fmaf(e1, r1.y, acc.y);
            acc.z = fmaf(e1, r1.z, acc.z); acc.w = fmaf(e1, r1.w, acc.w);
            acc.x = fmaf(e2, r2.x, acc.x); acc.y = fmaf(e2, r2.y, acc.y);
            acc.z = fmaf(e2, r2.z, acc.z); acc.w = fmaf(e2, r2.w, acc.w);
            acc.x = fmaf(e3, r3.x, acc.x); acc.y = fmaf(e3, r3.y, acc.y);
            acc.z = fmaf(e3, r3.z, acc.z); acc.w = fmaf(e3, r3.w, acc.w);
        }
        for (; j < end; j++) {
            int2 p = __ldg(d_epack + j);
            float w = __int_as_float(p.y);
            float4 r = *(const float4*)(t + (size_t)p.x * F + l4);
            acc.x = fmaf(w, r.x, acc.x); acc.y = fmaf(w, r.y, acc.y);
            acc.z = fmaf(w, r.z, acc.z); acc.w = fmaf(w, r.w, acc.w);
        }
        acc.x = fmaxf(acc.x + b.x, 0.0f);
        acc.y = fmaxf(acc.y + b.y, 0.0f);
        acc.z = fmaxf(acc.z + b.z, 0.0f);
        acc.w = fmaxf(acc.w + b.w, 0.0f);
        *(float4*)(h + (size_t)v * F + l4) = acc;
        s0 += acc.x; s1 += acc.y; s2 += acc.z; s3 += acc.w;
        q0 += acc.x * acc.x; q1 += acc.y * acc.y;
        q2 += acc.z * acc.z; q3 += acc.w * acc.w;
    }
    atomicAdd(&stats[l4 + 0], s0); atomicAdd(&stats[l4 + 1], s1);
    atomicAdd(&stats[l4 + 2], s2); atomicAdd(&stats[l4 + 3], s3);
    atomicAdd(&stats[F + l4 + 0], q0); atomicAdd(&stats[F + l4 + 1], q1);
    atomicAdd(&stats[F + l4 + 2], q2); atomicAdd(&stats[F + l4 + 3], q3);
}

// ---------------- fused aggregation (F=64, final) ----------------------------
__global__ __launch_bounds__(256) void k_agg64(const float* __restrict__ t,
                                               const float* __restrict__ bias,
                                               float* __restrict__ out, int n) {
    const int lane = threadIdx.x & 31;
    const int warp = (blockIdx.x * blockDim.x + threadIdx.x) >> 5;
    const int nwarp = (gridDim.x * blockDim.x) >> 5;
    float2 b = ((const float2*)bias)[lane];
    const int l2 = lane * 2;
    for (int v = warp; v < n; v += nwarp) {
        float dv = d_dinv[v];
        float w0 = dv * dv;
        float2 acc = *(const float2*)(t + (size_t)v * C_OUT + l2);
        acc.x *= w0; acc.y *= w0;
        int j = d_off[v];
        const int end = d_off[v + 1];
        for (; j + 4 <= end; j += 4) {
            int2 p0 = __ldg(d_epack + j),     p1 = __ldg(d_epack + j + 1);
            int2 p2 = __ldg(d_epack + j + 2), p3 = __ldg(d_epack + j + 3);
            float2 r0 = *(const float2*)(t + (size_t)p0.x * C_OUT + l2);
            float2 r1 = *(const float2*)(t + (size_t)p1.x * C_OUT + l2);
            float2 r2 = *(const float2*)(t + (size_t)p2.x * C_OUT + l2);
            float2 r3 = *(const float2*)(t + (size_t)p3.x * C_OUT + l2);
            float e0 = __int_as_float(p0.y), e1 = __int_as_float(p1.y);
            float e2 = __int_as_float(p2.y), e3 = __int_as_float(p3.y);
            acc.x = fmaf(e0, r0.x, acc.x); acc.y = fmaf(e0, r0.y, acc.y);
            acc.x = fmaf(e1, r1.x, acc.x); acc.y = fmaf(e1, r1.y, acc.y);
            acc.x = fmaf(e2, r2.x, acc.x); acc.y = fmaf(e2, r2.y, acc.y);
            acc.x = fmaf(e3, r3.x, acc.x); acc.y = fmaf(e3, r3.y, acc.y);
        }
        for (; j < end; j++) {
            int2 p = __ldg(d_epack + j);
            float w = __int_as_float(p.y);
            float2 r = *(const float2*)(t + (size_t)p.x * C_OUT + l2);
            acc.x = fmaf(w, r.x, acc.x); acc.y = fmaf(w, r.y, acc.y);
        }
        acc.x = fmaxf(acc.x + b.x, 0.0f);
        acc.y = fmaxf(acc.y + b.y, 0.0f);
        *(float2*)(out + (size_t)v * C_OUT + l2) = acc;
    }
}

// ---------------- BN ----------------------------------------------------------
__global__ void k_bn_finalize(const float* __restrict__ stats,
                              const float* __restrict__ gamma,
                              const float* __restrict__ beta,
                              float* __restrict__ scale, float* __restrict__ shift,
                              int n) {
    int c = threadIdx.x;                    // 128 threads
    float inv_n = 1.0f / (float)n;
    float m = stats[c] * inv_n;
    float var = stats[F + c] * inv_n - m * m;
    float rstd = rsqrtf(var + BN_EPS);
    float sc = gamma[c] * rstd;
    scale[c] = sc;
    shift[c] = beta[c] - sc * m;
}

// ---------------- launch ------------------------------------------------------
extern "C" void kernel_launch(void* const* d_in, const int* in_sizes, int n_in,
                              void* d_out, int out_size) {
    const float* x     = (const float*)d_in[0];
    const int*   ei    = (const int*)d_in[1];
    const float* W1    = (const float*)d_in[2];
    const float* b1    = (const float*)d_in[3];
    const float* W2    = (const float*)d_in[4];
    const float* b2    = (const float*)d_in[5];
    const float* Wout  = (const float*)d_in[6];
    const float* bout  = (const float*)d_in[7];
    const float* gamma = (const float*)d_in[8];
    const float* beta  = (const float*)d_in[9];
    float* out = (float*)d_out;

    const int n = in_sizes[0] / F;
    const int e = in_sizes[1] / 2;
    const int* src = ei;
    const int* dst = ei + e;
    const int nb = cdiv(n, 1024);

    float *t, *hr1, *hr2, *sc1, *sh1, *sc2, *sh2, *stats;
    float2 *wp1, *wp2;
    cudaGetSymbolAddress((void**)&t, d_t);
    cudaGetSymbolAddress((void**)&hr1, d_hr1);
    cudaGetSymbolAddress((void**)&hr2, d_hr2);
    cudaGetSymbolAddress((void**)&sc1, d_scale1);
    cudaGetSymbolAddress((void**)&sh1, d_shift1);
    cudaGetSymbolAddress((void**)&sc2, d_scale2);
    cudaGetSymbolAddress((void**)&sh2, d_shift2);
    cudaGetSymbolAddress((void**)&stats, d_stats);
    cudaGetSymbolAddress((void**)&wp1, d_Wp1);
    cudaGetSymbolAddress((void**)&wp2, d_Wp2);

    const int TB = 256;
    const int AGG_BLOCKS = 1024;
    const int prep_items = n + 4 * F + 64 * F * 2 + 192 * C_OUT;

    // 1: prep (zero cnt/stats, pack weights)
    k_prep<<<cdiv(prep_items, TB), TB>>>(W1, W2, Wout, n);
    // 2: degree histogram
    k_hist<<<cdiv(e, TB), TB>>>(dst, e);
    // 3: dinv
    k_dinv<<<cdiv(n, TB), TB>>>(n);
    // 4: layer-1 GEMM (profiled slot)
    k_gemm128s<false><<<cdiv(n, 64), TB>>>(x, wp1, t, n, nullptr, nullptr);
    // 5-7: hierarchical scan
    k_part<<<nb, TB>>>(n);
    k_part_scan<<<1, 128>>>(nb, n, e);
    k_off<<<nb, TB>>>(n);
    // 8: CSR scatter
    k_scatter<<<cdiv(e, TB), TB>>>(src, dst, e);
    // 9-10: layer-1 aggregation + BN
    k_agg128<<<AGG_BLOCKS, TB>>>(t, b1, hr1, n, stats);
    k_bn_finalize<<<1, 128>>>(stats, gamma, beta, sc1, sh1, n);
    // 11-13: layer-2
    k_gemm128s<true><<<cdiv(n, 64), TB>>>(hr1, wp2, t, n, sc1, sh1);
    k_agg128<<<AGG_BLOCKS, TB>>>(t, b2, hr2, n, stats + 2 * F);
    k_bn_finalize<<<1, 128>>>(stats + 2 * F, gamma, beta, sc2, sh2, n);
    // 14-15: output layer
    k_gemm_outs<<<cdiv(n, 128), TB>>>(x, hr1, hr2, t, n, sc1, sh1, sc2, sh2);
    k_agg64<<<AGG_BLOCKS, TB>>>(t, bout, out, n);
}